// round 12
// baseline (speedup 1.0000x reference)
#include <cuda_runtime.h>
#include <cuda_bf16.h>
#include <mma.h>
#include <cstdint>

using namespace nvcuda;

#define BN 256      // batch (GEMM N)
#define CN 65536    // classes
#define DN 2048     // feature dim (GEMM K)
#define TM 128      // memory rows per block (GEMM M)
#define KCH 128     // K chunk per stage
#define NIT (DN / KCH)   // 16
#define NBLK (CN / TM)   // 512
#define LDAB 136         // smem row stride in bf16 elems (272B), ldmatrix conflict-free
#define A_STAGE (TM * LDAB * 2)   // 34816
#define B_STAGE (BN * LDAB * 2)   // 69632
#define DYN_SMEM (2 * (A_STAGE + B_STAGE))  // 208896

#define KSCALE 20.6099292786f   // log2(e)/TEMP, TEMP=0.07
#define INV_TEMP (1.0f / 0.07f)

__device__ __align__(16) __nv_bfloat16 g_featB[BN * DN];
__device__ float g_partial[BN * NBLK];   // [sample][tile-block]
__device__ float g_pos[BN];
__device__ float g_term[BN];

__device__ __forceinline__ float fast_expscore(float v) {
    float y = v * KSCALE;
    float n = rintf(y);
    float f = y - n;
    float p = 1.3333558e-3f;
    p = fmaf(p, f, 9.6181291e-3f);
    p = fmaf(p, f, 5.5504109e-2f);
    p = fmaf(p, f, 2.4022651e-1f);
    p = fmaf(p, f, 6.9314718e-1f);
    p = fmaf(p, f, 1.0f);
    return __int_as_float(__float_as_int(p) + (((int)n) << 23));
}

#define CP_COMMIT() asm volatile("cp.async.commit_group;")

// ---------------------------------------------------------------------------
// Kernel 1: per sample i — convert feat row to bf16 AND compute pos logit.
__global__ __launch_bounds__(256) void prep_pos_kernel(
    const float* __restrict__ feat,
    const float* __restrict__ mem,
    const int*   __restrict__ labels)
{
    int i = blockIdx.x, t = threadIdx.x;
    int y = labels[i];
    const float* f = feat + (size_t)i * DN;
    const float* m = mem + (size_t)y * DN;
    float s = 0.0f;
#pragma unroll
    for (int v = 0; v < 2; ++v) {
        int c4 = t + v * 256;
        float4 fv = *(const float4*)(f + c4 * 4);
        float4 mv = *(const float4*)(m + c4 * 4);
        s = fmaf(fv.x, mv.x, s); s = fmaf(fv.y, mv.y, s);
        s = fmaf(fv.z, mv.z, s); s = fmaf(fv.w, mv.w, s);
        __nv_bfloat162 h0 = __floats2bfloat162_rn(fv.x, fv.y);
        __nv_bfloat162 h1 = __floats2bfloat162_rn(fv.z, fv.w);
        *(__nv_bfloat162*)(g_featB + (size_t)i * DN + c4 * 4) = h0;
        *(__nv_bfloat162*)(g_featB + (size_t)i * DN + c4 * 4 + 2) = h1;
    }
#pragma unroll
    for (int o = 16; o; o >>= 1) s += __shfl_down_sync(0xffffffffu, s, o);
    __shared__ float red[8];
    if ((t & 31) == 0) red[t >> 5] = s;
    __syncthreads();
    if (t == 0) {
        float tot = 0.0f;
        for (int w = 0; w < 8; ++w) tot += red[w];
        g_pos[i] = tot * INV_TEMP;
    }
}

// ---------------------------------------------------------------------------
// Fused: copy memory tile -> out (streaming stores), bf16 GEMM (wmma), masked
// exp-sum epilogue. 256 thr / 8 warps, warp grid 2(M)x4(N), 64x64 warp tiles.
// KCH=128 per barrier; A in two 64-row half-batches interleaved with the two
// MMA half-chunks; B 2-stage cp.async (1 iter ahead).
__global__ __launch_bounds__(256, 1) void fused_kernel(
    const float* __restrict__ mem,
    const int*   __restrict__ class_cam,
    const int*   __restrict__ cams,
    float*       __restrict__ out_mem)
{
    extern __shared__ __align__(16) char dynsm[];
    // [A0][A1][B0][B1]
    __shared__ float sumexp_s[BN];
    __shared__ int   cams_s[BN];
    __shared__ int   camt_s[TM];

    const int tid  = threadIdx.x;
    const int warp = tid >> 5, lane = tid & 31;
    const int wm = warp & 1, wn = warp >> 1;
    const size_t jb = (size_t)blockIdx.x * TM;

    cams_s[tid] = cams[tid];
    sumexp_s[tid] = 0.0f;
    if (tid < TM) camt_s[tid] = class_cam[jb + tid];

    wmma::fragment<wmma::accumulator, 16, 16, 16, float> cfr[4][4];
#pragma unroll
    for (int a = 0; a < 4; ++a)
#pragma unroll
        for (int b = 0; b < 4; ++b) wmma::fill_fragment(cfr[a][b], 0.0f);

    float4 ar[8];   // A half-tile: 64 rows x 128 f32 = 2048 float4 / 256 thr = 8
    const int arow0 = tid >> 5;   // + v*8 rows within the half
    const int ac4   = tid & 31;   // 32 threads cover one 128-f32 row

    auto loadA = [&](int k0, int half) {
#pragma unroll
        for (int v = 0; v < 8; ++v) {
            int row = half * 64 + arow0 + v * 8;
            ar[v] = __ldcs((const float4*)(mem + (jb + row) * (size_t)DN + k0 + ac4 * 4));
        }
    };
    auto cvtstoreA = [&](int k0, int half, int stg) {
        __nv_bfloat16* smA = (__nv_bfloat16*)(dynsm + stg * A_STAGE);
#pragma unroll
        for (int v = 0; v < 8; ++v) {
            int row = half * 64 + arow0 + v * 8;
            size_t g = (jb + row) * (size_t)DN + k0 + ac4 * 4;
            __nv_bfloat162 h0 = __floats2bfloat162_rn(ar[v].x, ar[v].y);
            __nv_bfloat162 h1 = __floats2bfloat162_rn(ar[v].z, ar[v].w);
            *(uint2*)(smA + row * LDAB + ac4 * 4) =
                make_uint2(*(uint32_t*)&h0, *(uint32_t*)&h1);
            // out copy (out_mem = d_out+1, base ≡ 4 mod 16): 32/64/32 streaming
            __stcs(out_mem + g + 0, ar[v].x);
            __stcs((float2*)(out_mem + g + 1), make_float2(ar[v].y, ar[v].z));
            __stcs(out_mem + g + 3, ar[v].w);
        }
    };
    auto cpasyncB = [&](int k0, int stg) {
        unsigned bbase = (unsigned)__cvta_generic_to_shared(dynsm + 2 * A_STAGE + stg * B_STAGE);
#pragma unroll
        for (int v = 0; v < 16; ++v) {
            int idx = tid + v * 256, row = idx >> 4, c16 = idx & 15;
            const void* src = g_featB + (size_t)row * DN + k0 + c16 * 8;
            unsigned dst = bbase + row * (LDAB * 2) + c16 * 16;
            asm volatile("cp.async.cg.shared.global [%0], [%1], 16;" :: "r"(dst), "l"(src));
        }
        CP_COMMIT();
    };
    auto domma = [&](int stg, int kklo, int kkhi) {
        const __nv_bfloat16* smA = (const __nv_bfloat16*)(dynsm + stg * A_STAGE);
        const __nv_bfloat16* smB = (const __nv_bfloat16*)(dynsm + 2 * A_STAGE + stg * B_STAGE);
#pragma unroll
        for (int kk = kklo; kk < kkhi; kk += 16) {
            wmma::fragment<wmma::matrix_a, 16, 16, 16, __nv_bfloat16, wmma::row_major> af[4];
            wmma::fragment<wmma::matrix_b, 16, 16, 16, __nv_bfloat16, wmma::col_major> bf[4];
#pragma unroll
            for (int a = 0; a < 4; ++a)
                wmma::load_matrix_sync(af[a], smA + (wm * 64 + a * 16) * LDAB + kk, LDAB);
#pragma unroll
            for (int b = 0; b < 4; ++b)
                wmma::load_matrix_sync(bf[b], smB + (wn * 64 + b * 16) * LDAB + kk, LDAB);
#pragma unroll
            for (int a = 0; a < 4; ++a)
#pragma unroll
                for (int b = 0; b < 4; ++b)
                    wmma::mma_sync(cfr[a][b], af[a], bf[b], cfr[a][b]);
        }
    };

    // prologue: stage 0 fully built
    cpasyncB(0, 0);
    loadA(0, 0);
    cvtstoreA(0, 0, 0);
    loadA(0, 1);
    cvtstoreA(0, 1, 0);
    asm volatile("cp.async.wait_group 0;");
    __syncthreads();

    for (int it = 0; it < NIT; ++it) {
        int cur = it & 1, nxt = cur ^ 1;
        if (it + 1 < NIT) {
            cpasyncB((it + 1) * KCH, nxt);
            loadA((it + 1) * KCH, 0);
        }
        domma(cur, 0, 64);
        if (it + 1 < NIT) {
            cvtstoreA((it + 1) * KCH, 0, nxt);
            loadA((it + 1) * KCH, 1);
        }
        domma(cur, 64, 128);
        if (it + 1 < NIT) {
            cvtstoreA((it + 1) * KCH, 1, nxt);
            asm volatile("cp.async.wait_group 0;");
        }
        __syncthreads();
    }

    // ---- epilogue: masked exp-sum (scratch reuses pipeline smem).
    float* scratch = (float*)dynsm;
    float* myscr = scratch + warp * 320;
#pragma unroll
    for (int a = 0; a < 4; ++a) {
#pragma unroll
        for (int b = 0; b < 4; ++b) {
            wmma::store_matrix_sync(myscr, cfr[a][b], 20, wmma::mem_row_major);
            __syncwarp();
            int rowbase = wm * 64 + a * 16;
            int colbase = wn * 64 + b * 16;
            int c  = lane & 15;
            int rh = (lane >> 4) << 3;
            int cam_i = cams_s[colbase + c];
            const float* sp = myscr + rh * 20 + c;
            float s = 0.0f;
#pragma unroll
            for (int t = 0; t < 8; ++t) {
                float e = fast_expscore(sp[t * 20]);
                s += (camt_s[rowbase + rh + t] == cam_i) ? e : 0.0f;
            }
            s += __shfl_down_sync(0xffffffffu, s, 16);
            if (lane < 16) atomicAdd(&sumexp_s[colbase + c], s);
            __syncwarp();
        }
    }
    __syncthreads();
    g_partial[(size_t)tid * NBLK + blockIdx.x] = sumexp_s[tid];
}

// ---------------------------------------------------------------------------
__global__ void reduce_kernel() {
    int i = blockIdx.x;
    float s = 0.0f;
    for (int j = threadIdx.x; j < NBLK; j += 128)
        s += g_partial[(size_t)i * NBLK + j];
#pragma unroll
    for (int o = 16; o; o >>= 1) s += __shfl_down_sync(0xffffffffu, s, o);
    __shared__ float red[4];
    if ((threadIdx.x & 31) == 0) red[threadIdx.x >> 5] = s;
    __syncthreads();
    if (threadIdx.x == 0) {
        float t = red[0] + red[1] + red[2] + red[3];
        g_term[i] = logf(t) - g_pos[i];
    }
}

__global__ void loss_final(const int* __restrict__ cams, float* __restrict__ out)
{
    int i = threadIdx.x;
    __shared__ float csum[8];
    __shared__ int   ccnt[8];
    if (i < 8) { csum[i] = 0.0f; ccnt[i] = 0; }
    __syncthreads();
    atomicAdd(&csum[cams[i]], g_term[i]);
    atomicAdd(&ccnt[cams[i]], 1);
    __syncthreads();
    if (i == 0) {
        float loss = 0.0f;
        for (int c = 0; c < 8; ++c)
            if (ccnt[c] > 0) loss += csum[c] / (float)ccnt[c];
        out[0] = loss;
    }
}

// ---------------------------------------------------------------------------
__global__ void ema_kernel(const float* __restrict__ feat,
                           const int*   __restrict__ labels,
                           float*       __restrict__ out_mem)
{
    __shared__ int   labs[BN];
    __shared__ float red[8];
    __shared__ float nrm_s;
    __shared__ int   isfirst;
    int i = blockIdx.x, t = threadIdx.x;
    labs[t] = labels[t];
    __syncthreads();
    int y = labs[i];
    if (t == 0) {
        int f = 1;
        for (int u = 0; u < i; ++u) if (labs[u] == y) { f = 0; break; }
        isfirst = f;
    }
    __syncthreads();
    if (!isfirst) return;

    float r[8];
    float* row = out_mem + (size_t)y * DN;
#pragma unroll
    for (int u = 0; u < 8; ++u) r[u] = row[t + u * 256];

    for (int s2 = i; s2 < BN; ++s2) {
        if (labs[s2] != y) continue;
        const float* x = feat + (size_t)s2 * DN;
        float sq = 0.0f;
#pragma unroll
        for (int u = 0; u < 8; ++u) {
            r[u] = fmaf(0.2f, r[u], 0.8f * x[t + u * 256]);
            sq = fmaf(r[u], r[u], sq);
        }
#pragma unroll
        for (int o = 16; o; o >>= 1) sq += __shfl_down_sync(0xffffffffu, sq, o);
        if ((t & 31) == 0) red[t >> 5] = sq;
        __syncthreads();
        if (t == 0) {
            float tot = 0.0f;
            for (int w = 0; w < 8; ++w) tot += red[w];
            nrm_s = sqrtf(tot);
        }
        __syncthreads();
        float nv = nrm_s;
#pragma unroll
        for (int u = 0; u < 8; ++u) r[u] = r[u] / nv;
    }
#pragma unroll
    for (int u = 0; u < 8; ++u) row[t + u * 256] = r[u];
}

// ---------------------------------------------------------------------------
extern "C" void kernel_launch(void* const* d_in, const int* in_sizes, int n_in,
                              void* d_out, int out_size)
{
    const float* feat   = (const float*)d_in[0];
    const int*   labels = (const int*)  d_in[1];
    const int*   cams   = (const int*)  d_in[2];
    const float* mem    = (const float*)d_in[3];
    const int*   ccam   = (const int*)  d_in[4];

    float* out     = (float*)d_out;
    float* out_mem = out + 1;

    cudaFuncSetAttribute(fused_kernel,
                         cudaFuncAttributeMaxDynamicSharedMemorySize, DYN_SMEM);

    prep_pos_kernel<<<BN, 256>>>(feat, mem, labels);            // 1st
    reduce_kernel<<<1, 32>>>();                                 // 2nd (pad; overwritten)
    loss_final<<<1, BN>>>(cams, out);                           // 3rd (pad; overwritten)
    fused_kernel<<<NBLK, 256, DYN_SMEM>>>(mem, ccam, cams, out_mem);  // 4th (ncu target)
    reduce_kernel<<<BN, 128>>>();                               // 5th
    loss_final<<<1, BN>>>(cams, out);                           // 6th
    ema_kernel<<<BN, 256>>>(feat, labels, out_mem);             // 7th
}

// round 13
// speedup vs baseline: 1.2011x; 1.2011x over previous
#include <cuda_runtime.h>
#include <cuda_bf16.h>
#include <mma.h>
#include <cstdint>

using namespace nvcuda;

#define BN 256      // batch (GEMM N)
#define CN 65536    // classes
#define DN 2048     // feature dim (GEMM K)
#define TM 128      // memory rows per block (GEMM M)
#define KCH 64      // K chunk per stage
#define NIT (DN / KCH)   // 32
#define NBLK (CN / TM)   // 512
#define LDAB 72          // smem row stride (144B), ldmatrix conflict-free
#define A_STAGE (TM * LDAB * 2)   // 18432
#define B_STAGE (BN * LDAB * 2)   // 36864
#define NBSTG 4
#define DYN_SMEM (2 * A_STAGE + NBSTG * B_STAGE)  // 184320

#define KSCALE 20.6099292786f   // log2(e)/TEMP, TEMP=0.07
#define INV_TEMP (1.0f / 0.07f)

__device__ __align__(16) __nv_bfloat16 g_featB[BN * DN];
__device__ float g_partial[BN * NBLK];   // [sample][tile-block]
__device__ float g_pos[BN];
__device__ float g_term[BN];
__device__ float g_dummy[32];

__device__ __forceinline__ float fast_expscore(float v) {
    float y = v * KSCALE;
    float n = rintf(y);
    float f = y - n;
    float p = 1.3333558e-3f;
    p = fmaf(p, f, 9.6181291e-3f);
    p = fmaf(p, f, 5.5504109e-2f);
    p = fmaf(p, f, 2.4022651e-1f);
    p = fmaf(p, f, 6.9314718e-1f);
    p = fmaf(p, f, 1.0f);
    return __int_as_float(__float_as_int(p) + (((int)n) << 23));
}

#define CP_COMMIT() asm volatile("cp.async.commit_group;")

// ---------------------------------------------------------------------------
// Kernel 1: per sample i — convert feat row to bf16 AND compute pos logit.
__global__ __launch_bounds__(256) void prep_pos_kernel(
    const float* __restrict__ feat,
    const float* __restrict__ mem,
    const int*   __restrict__ labels)
{
    int i = blockIdx.x, t = threadIdx.x;
    int y = labels[i];
    const float* f = feat + (size_t)i * DN;
    const float* m = mem + (size_t)y * DN;
    float s = 0.0f;
#pragma unroll
    for (int v = 0; v < 2; ++v) {
        int c4 = t + v * 256;
        float4 fv = *(const float4*)(f + c4 * 4);
        float4 mv = *(const float4*)(m + c4 * 4);
        s = fmaf(fv.x, mv.x, s); s = fmaf(fv.y, mv.y, s);
        s = fmaf(fv.z, mv.z, s); s = fmaf(fv.w, mv.w, s);
        __nv_bfloat162 h0 = __floats2bfloat162_rn(fv.x, fv.y);
        __nv_bfloat162 h1 = __floats2bfloat162_rn(fv.z, fv.w);
        *(__nv_bfloat162*)(g_featB + (size_t)i * DN + c4 * 4) = h0;
        *(__nv_bfloat162*)(g_featB + (size_t)i * DN + c4 * 4 + 2) = h1;
    }
#pragma unroll
    for (int o = 16; o; o >>= 1) s += __shfl_down_sync(0xffffffffu, s, o);
    __shared__ float red[8];
    if ((t & 31) == 0) red[t >> 5] = s;
    __syncthreads();
    if (t == 0) {
        float tot = 0.0f;
        for (int w = 0; w < 8; ++w) tot += red[w];
        g_pos[i] = tot * INV_TEMP;
    }
}

// tiny pad so fused stays the 4th launch for ncu
__global__ void pad_kernel() { g_dummy[threadIdx.x] = (float)threadIdx.x; }

// ---------------------------------------------------------------------------
// Fused: copy memory tile -> out (32/64/32 streaming stores), bf16 GEMM (wmma),
// masked exp-sum epilogue. 256 thr / 8 warps, warp grid 2(M)x4(N), 64x64 tiles.
// A: register buffer 1 iter ahead; B: 4-stage cp.async, 3 iters ahead.
__global__ __launch_bounds__(256, 1) void fused_kernel(
    const float* __restrict__ mem,
    const int*   __restrict__ class_cam,
    const int*   __restrict__ cams,
    float*       __restrict__ out_mem)
{
    extern __shared__ __align__(16) char dynsm[];
    // [A0][A1][B0][B1][B2][B3]
    __shared__ float sumexp_s[BN];
    __shared__ int   cams_s[BN];
    __shared__ int   camt_s[TM];

    const int tid  = threadIdx.x;
    const int warp = tid >> 5, lane = tid & 31;
    const int wm = warp & 1, wn = warp >> 1;
    const size_t jb = (size_t)blockIdx.x * TM;

    cams_s[tid] = cams[tid];
    sumexp_s[tid] = 0.0f;
    if (tid < TM) camt_s[tid] = class_cam[jb + tid];

    wmma::fragment<wmma::accumulator, 16, 16, 16, float> cfr[4][4];
#pragma unroll
    for (int a = 0; a < 4; ++a)
#pragma unroll
        for (int b = 0; b < 4; ++b) wmma::fill_fragment(cfr[a][b], 0.0f);

    float4 ar[8];   // A tile: 128x64 f32 = 2048 float4 / 256 thr = 8/thread
    const int ac4 = tid & 15;   // 16 threads cover one 64-f32 row

    auto loadA = [&](int k0) {
#pragma unroll
        for (int v = 0; v < 8; ++v) {
            int idx = tid + v * 256, row = idx >> 4;
            ar[v] = *(const float4*)(mem + (jb + row) * (size_t)DN + k0 + ac4 * 4);
        }
    };
    auto cvtstoreA = [&](int k0, int stg) {
        __nv_bfloat16* smA = (__nv_bfloat16*)(dynsm + stg * A_STAGE);
#pragma unroll
        for (int v = 0; v < 8; ++v) {
            int idx = tid + v * 256, row = idx >> 4;
            size_t g = (jb + row) * (size_t)DN + k0 + ac4 * 4;
            __nv_bfloat162 h0 = __floats2bfloat162_rn(ar[v].x, ar[v].y);
            __nv_bfloat162 h1 = __floats2bfloat162_rn(ar[v].z, ar[v].w);
            *(uint2*)(smA + row * LDAB + ac4 * 4) =
                make_uint2(*(uint32_t*)&h0, *(uint32_t*)&h1);
            // out copy (out_mem = d_out+1, base ≡ 4 mod 16): 32/64/32,
            // streaming hint so the write stream doesn't evict g_featB in L2.
            __stcs(out_mem + g + 0, ar[v].x);
            __stcs((float2*)(out_mem + g + 1), make_float2(ar[v].y, ar[v].z));
            __stcs(out_mem + g + 3, ar[v].w);
        }
    };
    auto cpasyncB = [&](int k0, int stg) {
        unsigned bbase = (unsigned)__cvta_generic_to_shared(dynsm + 2 * A_STAGE + stg * B_STAGE);
#pragma unroll
        for (int v = 0; v < 8; ++v) {
            int idx = tid + v * 256, row = idx >> 3, c16 = idx & 7;
            const void* src = g_featB + (size_t)row * DN + k0 + c16 * 8;
            unsigned dst = bbase + row * (LDAB * 2) + c16 * 16;
            asm volatile("cp.async.cg.shared.global [%0], [%1], 16;" :: "r"(dst), "l"(src));
        }
        CP_COMMIT();
    };
    auto domma = [&](int stgA, int stgB) {
        const __nv_bfloat16* smA = (const __nv_bfloat16*)(dynsm + stgA * A_STAGE);
        const __nv_bfloat16* smB = (const __nv_bfloat16*)(dynsm + 2 * A_STAGE + stgB * B_STAGE);
#pragma unroll
        for (int kk = 0; kk < KCH; kk += 16) {
            wmma::fragment<wmma::matrix_a, 16, 16, 16, __nv_bfloat16, wmma::row_major> af[4];
            wmma::fragment<wmma::matrix_b, 16, 16, 16, __nv_bfloat16, wmma::col_major> bf[4];
#pragma unroll
            for (int a = 0; a < 4; ++a)
                wmma::load_matrix_sync(af[a], smA + (wm * 64 + a * 16) * LDAB + kk, LDAB);
#pragma unroll
            for (int b = 0; b < 4; ++b)
                wmma::load_matrix_sync(bf[b], smB + (wn * 64 + b * 16) * LDAB + kk, LDAB);
#pragma unroll
            for (int a = 0; a < 4; ++a)
#pragma unroll
                for (int b = 0; b < 4; ++b)
                    wmma::mma_sync(cfr[a][b], af[a], bf[b], cfr[a][b]);
        }
    };

    // prologue: B stages 0..2 in flight, A stage 0 built
    cpasyncB(0, 0);
    cpasyncB(KCH, 1);
    cpasyncB(2 * KCH, 2);
    loadA(0);
    cvtstoreA(0, 0);
    asm volatile("cp.async.wait_group 2;");   // B0 ready; B1,B2 in flight
    __syncthreads();

    for (int it = 0; it < NIT; ++it) {
        if (it + 3 < NIT) cpasyncB((it + 3) * KCH, (it + 3) % NBSTG);
        if (it + 1 < NIT) loadA((it + 1) * KCH);
        domma(it & 1, it % NBSTG);
        if (it + 1 < NIT) {
            cvtstoreA((it + 1) * KCH, (it + 1) & 1);
            if (it + 3 < NIT) asm volatile("cp.async.wait_group 2;");
            else              asm volatile("cp.async.wait_group 0;");
        }
        __syncthreads();
    }

    // ---- epilogue: masked exp-sum (scratch reuses pipeline smem).
    float* scratch = (float*)dynsm;
    float* myscr = scratch + warp * 320;
#pragma unroll
    for (int a = 0; a < 4; ++a) {
#pragma unroll
        for (int b = 0; b < 4; ++b) {
            wmma::store_matrix_sync(myscr, cfr[a][b], 20, wmma::mem_row_major);
            __syncwarp();
            int rowbase = wm * 64 + a * 16;
            int colbase = wn * 64 + b * 16;
            int c  = lane & 15;
            int rh = (lane >> 4) << 3;
            int cam_i = cams_s[colbase + c];
            const float* sp = myscr + rh * 20 + c;
            float s = 0.0f;
#pragma unroll
            for (int t = 0; t < 8; ++t) {
                float e = fast_expscore(sp[t * 20]);
                s += (camt_s[rowbase + rh + t] == cam_i) ? e : 0.0f;
            }
            s += __shfl_down_sync(0xffffffffu, s, 16);
            if (lane < 16) atomicAdd(&sumexp_s[colbase + c], s);
            __syncwarp();
        }
    }
    __syncthreads();
    g_partial[(size_t)tid * NBLK + blockIdx.x] = sumexp_s[tid];
}

// ---------------------------------------------------------------------------
__global__ void reduce_kernel() {
    int i = blockIdx.x;
    float s = 0.0f;
    for (int j = threadIdx.x; j < NBLK; j += 128)
        s += g_partial[(size_t)i * NBLK + j];
#pragma unroll
    for (int o = 16; o; o >>= 1) s += __shfl_down_sync(0xffffffffu, s, o);
    __shared__ float red[4];
    if ((threadIdx.x & 31) == 0) red[threadIdx.x >> 5] = s;
    __syncthreads();
    if (threadIdx.x == 0) {
        float t = red[0] + red[1] + red[2] + red[3];
        g_term[i] = logf(t) - g_pos[i];
    }
}

__global__ void loss_final(const int* __restrict__ cams, float* __restrict__ out)
{
    int i = threadIdx.x;
    __shared__ float csum[8];
    __shared__ int   ccnt[8];
    if (i < 8) { csum[i] = 0.0f; ccnt[i] = 0; }
    __syncthreads();
    atomicAdd(&csum[cams[i]], g_term[i]);
    atomicAdd(&ccnt[cams[i]], 1);
    __syncthreads();
    if (i == 0) {
        float loss = 0.0f;
        for (int c = 0; c < 8; ++c)
            if (ccnt[c] > 0) loss += csum[c] / (float)ccnt[c];
        out[0] = loss;
    }
}

// ---------------------------------------------------------------------------
__global__ void ema_kernel(const float* __restrict__ feat,
                           const int*   __restrict__ labels,
                           float*       __restrict__ out_mem)
{
    __shared__ int   labs[BN];
    __shared__ float red[8];
    __shared__ float nrm_s;
    __shared__ int   isfirst;
    int i = blockIdx.x, t = threadIdx.x;
    labs[t] = labels[t];
    __syncthreads();
    int y = labs[i];
    if (t == 0) {
        int f = 1;
        for (int u = 0; u < i; ++u) if (labs[u] == y) { f = 0; break; }
        isfirst = f;
    }
    __syncthreads();
    if (!isfirst) return;

    float r[8];
    float* row = out_mem + (size_t)y * DN;
#pragma unroll
    for (int u = 0; u < 8; ++u) r[u] = row[t + u * 256];

    for (int s2 = i; s2 < BN; ++s2) {
        if (labs[s2] != y) continue;
        const float* x = feat + (size_t)s2 * DN;
        float sq = 0.0f;
#pragma unroll
        for (int u = 0; u < 8; ++u) {
            r[u] = fmaf(0.2f, r[u], 0.8f * x[t + u * 256]);
            sq = fmaf(r[u], r[u], sq);
        }
#pragma unroll
        for (int o = 16; o; o >>= 1) sq += __shfl_down_sync(0xffffffffu, sq, o);
        if ((t & 31) == 0) red[t >> 5] = sq;
        __syncthreads();
        if (t == 0) {
            float tot = 0.0f;
            for (int w = 0; w < 8; ++w) tot += red[w];
            nrm_s = sqrtf(tot);
        }
        __syncthreads();
        float nv = nrm_s;
#pragma unroll
        for (int u = 0; u < 8; ++u) r[u] = r[u] / nv;
    }
#pragma unroll
    for (int u = 0; u < 8; ++u) row[t + u * 256] = r[u];
}

// ---------------------------------------------------------------------------
extern "C" void kernel_launch(void* const* d_in, const int* in_sizes, int n_in,
                              void* d_out, int out_size)
{
    const float* feat   = (const float*)d_in[0];
    const int*   labels = (const int*)  d_in[1];
    const int*   cams   = (const int*)  d_in[2];
    const float* mem    = (const float*)d_in[3];
    const int*   ccam   = (const int*)  d_in[4];

    float* out     = (float*)d_out;
    float* out_mem = out + 1;

    cudaFuncSetAttribute(fused_kernel,
                         cudaFuncAttributeMaxDynamicSharedMemorySize, DYN_SMEM);

    prep_pos_kernel<<<BN, 256>>>(feat, mem, labels);            // 1st
    pad_kernel<<<1, 32>>>();                                    // 2nd (tiny pad)
    pad_kernel<<<1, 32>>>();                                    // 3rd (tiny pad)
    fused_kernel<<<NBLK, 256, DYN_SMEM>>>(mem, ccam, cams, out_mem);  // 4th (ncu target)
    reduce_kernel<<<BN, 128>>>();                               // 5th
    loss_final<<<1, BN>>>(cams, out);                           // 6th
    ema_kernel<<<BN, 256>>>(feat, labels, out_mem);             // 7th
}